// round 14
// baseline (speedup 1.0000x reference)
#include <cuda_runtime.h>
#include <cuda_fp16.h>

#define NUM_USERS 50000
#define NUM_ITEMS 100000
#define NUM_NODES 150000   // NUM_USERS + NUM_ITEMS
#define LATENT_DIM 64
#define NNZ 4800000
#define BATCH 4096

// Scratch (allocation-free, graph-capturable). fp16 buffers: h0 = input
// embeddings, h1/h2 = layer outputs (128B/row = 32 half2 each).
// Layer 3 is never materialized: computed on the fly in the dot kernel.
__device__ unsigned g_h0[NUM_NODES * 32];
__device__ unsigned g_h1[NUM_NODES * 32];
__device__ unsigned g_h2[NUM_NODES * 32];
__device__ int      g_row_ptr[NUM_NODES + 1];

__device__ __forceinline__ unsigned h2_as_u32(__half2 h)
{
    return *reinterpret_cast<unsigned*>(&h);
}
__device__ __forceinline__ __half2 u32_as_h2(unsigned u)
{
    return *reinterpret_cast<__half2*>(&u);
}

// ---------------------------------------------------------------------------
// Init: concat(user_emb, item_emb) -> g_h0 (fp16). One thread per 4 dims.
// ---------------------------------------------------------------------------
__global__ void __launch_bounds__(256) init_kernel(const float4* __restrict__ user_emb,
                                                   const float4* __restrict__ item_emb)
{
    const int total  = NUM_NODES * LATENT_DIM / 4;
    const int uquads = NUM_USERS * LATENT_DIM / 4;
    int i = blockIdx.x * blockDim.x + threadIdx.x;
    if (i >= total) return;
    float4 v = (i < uquads) ? __ldg(&user_emb[i]) : __ldg(&item_emb[i - uquads]);
    uint2 p;
    p.x = h2_as_u32(__floats2half2_rn(v.x, v.y));
    p.y = h2_as_u32(__floats2half2_rn(v.z, v.w));
    reinterpret_cast<uint2*>(g_h0)[i] = p;
}

// ---------------------------------------------------------------------------
// Build CSR row_ptr from sorted edge_rows.
// ---------------------------------------------------------------------------
__global__ void __launch_bounds__(256) rowptr_kernel(const int* __restrict__ rows)
{
    int e = blockIdx.x * blockDim.x + threadIdx.x;
    if (e >= NNZ) return;
    int r  = rows[e];
    int rp = (e == 0) ? -1 : rows[e - 1];
    for (int rr = rp + 1; rr <= r; ++rr) g_row_ptr[rr] = e;
    if (e == NNZ - 1) {
        for (int rr = r + 1; rr <= NUM_NODES; ++rr) g_row_ptr[rr] = NNZ;
    }
}

// ---------------------------------------------------------------------------
// SpMM (fp16 gather, fp32 accumulate): warp per row, full warp per edge.
// Lane L owns dims (2L, 2L+1): gather = one half2 LDG.32 (the 32 lanes cover
// the whole 128B row, 1 L1 wavefront/edge); no cross-lane reduction.
// Metadata: staged per 32-edge chunk; each lane writes one {col<<7, val}
// int2 (byte offset pre-shifted), and the inner loop reads PAIRS of edges
// with one broadcast LDS.128 (native int4 array) — half the LDS wavefronts
// of one-LDS-per-edge. Two independent accumulator chains (even/odd edge);
// 8 gathers in flight per unrolled block. Stage zero-fills entries past n,
// so the inner loop is branchless (dead edges gather row 0 with val 0).
// ---------------------------------------------------------------------------
__global__ void __launch_bounds__(256) spmm_kernel(const int*   __restrict__ cols,
                                                   const float* __restrict__ vals,
                                                   int which)
{
    __shared__ int4 meta4[8][16];    // 8 warps x 16 int4 = 32 staged edges

    const unsigned* __restrict__ xin  = (which == 0) ? g_h0 : g_h1;
    unsigned*       __restrict__ xout = (which == 0) ? g_h1 : g_h2;

    int warp = (blockIdx.x * blockDim.x + threadIdx.x) >> 5;
    int lane = threadIdx.x & 31;
    int wib  = (threadIdx.x >> 5);
    if (warp >= NUM_NODES) return;

    const int start = g_row_ptr[warp];
    const int end   = g_row_ptr[warp + 1];

    // lane-fixed byte base: row byte-offset (c<<7) is added per edge
    const char* __restrict__ xb = reinterpret_cast<const char*>(xin) + lane * 4;
    const int4* mrow4 = meta4[wib];
    int2*       mrow2 = reinterpret_cast<int2*>(meta4[wib]);   // write view

    float2 sE = make_float2(0.f, 0.f);   // even-edge chain
    float2 sO = make_float2(0.f, 0.f);   // odd-edge chain

    for (int base = start; base < end; base += 32) {
        const int n = min(32, end - base);          // warp-uniform
        int2 m = make_int2(0, 0);                   // zero-pad: row 0, val 0
        if (lane < n)
            m = make_int2(__ldg(&cols[base + lane]) << 7,
                          __float_as_int(__ldg(&vals[base + lane])));
        __syncwarp();                               // prior chunk reads done
        mrow2[lane] = m;
        __syncwarp();

        const int mcount = (n + 7) & ~7;            // padded, branchless
        for (int j = 0; j < mcount; j += 8) {
            #pragma unroll
            for (int kk = 0; kk < 4; ++kk) {        // 4 LDS.128 = 8 edges
                int4 e2 = mrow4[(j >> 1) + kk];     // {c0<<7, v0, c1<<7, v1}
                unsigned x0 = *reinterpret_cast<const unsigned*>(xb + e2.x);
                unsigned x1 = *reinterpret_cast<const unsigned*>(xb + e2.z);
                float v0 = __int_as_float(e2.y);
                float v1 = __int_as_float(e2.w);
                float2 f0 = __half22float2(u32_as_h2(x0));
                float2 f1 = __half22float2(u32_as_h2(x1));
                sE.x += v0 * f0.x;  sE.y += v0 * f0.y;
                sO.x += v1 * f1.x;  sO.y += v1 * f1.y;
            }
        }
    }

    float2 s = make_float2(sE.x + sO.x, sE.y + sO.y);
    xout[(size_t)warp * 32 + lane] = h2_as_u32(__floats2half2_rn(s.x, s.y));
}

// ---------------------------------------------------------------------------
// Compute one layer-3 row on the fly from h2 (fp32, never rounded):
// e3[node] dims (2L, 2L+1). Shfl-staged (only 8192 rows computed).
// ---------------------------------------------------------------------------
__device__ __forceinline__ float2 spmm_row_h2(const int*   __restrict__ cols,
                                              const float* __restrict__ vals,
                                              int node, int lane)
{
    const unsigned FULL = 0xffffffffu;
    const int start = g_row_ptr[node];
    const int end   = g_row_ptr[node + 1];
    const unsigned* __restrict__ xq = g_h2 + lane;

    float2 s = make_float2(0.f, 0.f);
    for (int base = start; base < end; base += 32) {
        const int n = min(32, end - base);
        int   c = 0;
        float v = 0.f;
        if (lane < n) {
            c = __ldg(&cols[base + lane]);
            v = __ldg(&vals[base + lane]);
        }
        for (int j = 0; j < n; j += 8) {
            #pragma unroll
            for (int k = 0; k < 8; ++k) {           // j+k <= 31
                int   cc = __shfl_sync(FULL, c, j + k);
                float vv = __shfl_sync(FULL, v, j + k);
                if (j + k >= n) vv = 0.f;
                unsigned x = __ldg(&xq[(size_t)cc * 32]);
                float2 f = __half22float2(u32_as_h2(x));
                s.x += vv * f.x;
                s.y += vv * f.y;
            }
        }
    }
    return s;
}

// ---------------------------------------------------------------------------
// Fused layer-3 + dot: acc = e0 + e1 + e2 + e3 for the two sampled nodes,
// dot, /16 (the two /4 layer norms folded). Warp per element.
// ---------------------------------------------------------------------------
__global__ void __launch_bounds__(256) dot_kernel(const float2* __restrict__ user_emb,
                                                  const float2* __restrict__ item_emb,
                                                  const int*    __restrict__ users,
                                                  const int*    __restrict__ items,
                                                  const int*    __restrict__ cols,
                                                  const float*  __restrict__ vals,
                                                  float* __restrict__ out)
{
    int warp = (blockIdx.x * blockDim.x + threadIdx.x) >> 5;
    int lane = threadIdx.x & 31;
    if (warp >= BATCH) return;

    const int u  = users[warp];
    const int it = items[warp];
    const int un = u;                       // user node id
    const int in = it + NUM_USERS;          // item node id

    float2 ua = __ldg(&user_emb[(size_t)u * 32 + lane]);
    {
        float2 f1 = __half22float2(u32_as_h2(__ldg(&g_h1[(size_t)un * 32 + lane])));
        float2 f2 = __half22float2(u32_as_h2(__ldg(&g_h2[(size_t)un * 32 + lane])));
        float2 f3 = spmm_row_h2(cols, vals, un, lane);
        ua.x += f1.x + f2.x + f3.x;
        ua.y += f1.y + f2.y + f3.y;
    }

    float2 ia = __ldg(&item_emb[(size_t)it * 32 + lane]);
    {
        float2 f1 = __half22float2(u32_as_h2(__ldg(&g_h1[(size_t)in * 32 + lane])));
        float2 f2 = __half22float2(u32_as_h2(__ldg(&g_h2[(size_t)in * 32 + lane])));
        float2 f3 = spmm_row_h2(cols, vals, in, lane);
        ia.x += f1.x + f2.x + f3.x;
        ia.y += f1.y + f2.y + f3.y;
    }

    float s = ua.x * ia.x + ua.y * ia.y;

    #pragma unroll
    for (int o = 16; o > 0; o >>= 1)
        s += __shfl_xor_sync(0xffffffffu, s, o);

    if (lane == 0) out[warp] = s * (1.0f / 16.0f);
}

// ---------------------------------------------------------------------------
extern "C" void kernel_launch(void* const* d_in, const int* in_sizes, int n_in,
                              void* d_out, int out_size)
{
    const float* user_emb  = (const float*)d_in[0];
    const float* item_emb  = (const float*)d_in[1];
    const int*   edge_rows = (const int*)  d_in[2];
    const int*   edge_cols = (const int*)  d_in[3];
    const float* edge_vals = (const float*)d_in[4];
    const int*   users     = (const int*)  d_in[5];
    const int*   items     = (const int*)  d_in[6];
    float*       out       = (float*)d_out;

    (void)in_sizes; (void)n_in; (void)out_size;

    {
        int total = NUM_NODES * LATENT_DIM / 4;
        init_kernel<<<(total + 255) / 256, 256>>>(
            reinterpret_cast<const float4*>(user_emb),
            reinterpret_cast<const float4*>(item_emb));
    }

    rowptr_kernel<<<(NNZ + 255) / 256, 256>>>(edge_rows);

    {
        int blocks = (NUM_NODES * 32 + 255) / 256;   // warp per row
        spmm_kernel<<<blocks, 256>>>(edge_cols, edge_vals, 0);  // h0 -> h1
        spmm_kernel<<<blocks, 256>>>(edge_cols, edge_vals, 1);  // h1 -> h2
    }

    dot_kernel<<<(BATCH * 32 + 255) / 256, 256>>>(
        reinterpret_cast<const float2*>(user_emb),
        reinterpret_cast<const float2*>(item_emb),
        users, items, edge_cols, edge_vals, out);
}